// round 11
// baseline (speedup 1.0000x reference)
#include <cuda_runtime.h>

#define T_STEPS 16
#define BATCH   32
#define HH      256
#define WW      256
#define NPIX    (BATCH*HH*WW)       // 2,097,152 pixels
#define TILE    32
#define NTILES  (BATCH*8*8)         // 2048 tiles
#define E2W     36                  // tile + 2*2 halo (layer-1 spike extent)
#define E1W     34                  // tile + 2*1 halo (layer-2 extent)
#define E2A     (E2W*E2W)           // 1296
#define E1A     (E1W*E1W)           // 1156
#define NTH     320                 // K2: 10 warps
#define NWARPS  (NTH/32)
#define NS2     5                   // ceil(1296/320)
#define NBLK    289                 // 17x17 2x2-pixel blocks covering E1
#define K1TH    256                 // K1 threads per block

// 4 MB spike scratch: bit t of g_spk[p] = layer-1 spike at pixel p, time t
__device__ unsigned short g_spk[NPIX];
// per-tile any-spike flags (tile = (b*8 + ty)*8 + tx)
__device__ unsigned g_any[NTILES];

// ==================== K0: zero the per-tile flags =======================
__global__ void zero_flags_kernel()
{
    int i = blockIdx.x * 256 + threadIdx.x;
    if (i < NTILES) g_any[i] = 0u;
}

// ========================= K1: pointwise LIF-1 ==========================
// 4 pixels per thread via float4: 16 LDG.128 (MLP=16), recurrence in regs,
// one 8-byte packed spike store, per-8-lane-group flag atomicOr.
__global__ void __launch_bounds__(K1TH) lif1_kernel(const float* __restrict__ x)
{
    const int tid = threadIdx.x;
    const int p4  = (blockIdx.x * K1TH + tid) * 4;

    float4 xv[T_STEPS];
#pragma unroll
    for (int t = 0; t < T_STEPS; ++t)
        xv[t] = __ldg((const float4*)(x + (size_t)t * NPIX + p4));

    float v0 = 0.f, v1 = 0.f, v2 = 0.f, v3 = 0.f;
    unsigned b0 = 0u, b1 = 0u, b2 = 0u, b3 = 0u;
#pragma unroll
    for (int t = 0; t < T_STEPS; ++t) {
        // v = v + (x-v)/2 : single-rounded, bit-identical to reference
        v0 = fmaf(xv[t].x - v0, 0.5f, v0);
        if (v0 >= 1.0f) { b0 |= 1u << t; v0 = 0.0f; }
        v1 = fmaf(xv[t].y - v1, 0.5f, v1);
        if (v1 >= 1.0f) { b1 |= 1u << t; v1 = 0.0f; }
        v2 = fmaf(xv[t].z - v2, 0.5f, v2);
        if (v2 >= 1.0f) { b2 |= 1u << t; v2 = 0.0f; }
        v3 = fmaf(xv[t].w - v3, 0.5f, v3);
        if (v3 >= 1.0f) { b3 |= 1u << t; v3 = 0.0f; }
    }

    uint2 pk;
    pk.x = b0 | (b1 << 16);
    pk.y = b2 | (b3 << 16);
    *(uint2*)(g_spk + p4) = pk;       // 8B aligned (p4 % 4 == 0)

    // per-tile flag: 8 consecutive lanes cover one 32-pixel tile row chunk
    unsigned m = b0 | b1 | b2 | b3;
    unsigned a = __ballot_sync(0xffffffffu, m != 0u);
    int lane = tid & 31;
    if ((lane & 7) == 0 && ((a >> (lane & ~7)) & 0xFFu)) {
        int xc = p4 & 255;
        int y  = (p4 >> 8) & 255;
        int b  = p4 >> 16;
        atomicOr(&g_any[(b * 8 + (y >> 5)) * 8 + (xc >> 5)], 1u);
    }
}

// ==================== K2: bit-domain LIF-2 + convs ======================
__global__ void __launch_bounds__(NTH, 3) lif2_kernel(
    const float* __restrict__ w1,
    const float* __restrict__ w2,
    float* __restrict__ out)
{
    __shared__ unsigned short     SW[E2A];            // spike words (16 t)
    __shared__ unsigned           WANY[NWARPS];
    __shared__ unsigned           FLAG;
    __shared__ unsigned long long ROWS[T_STEPS][E2W]; // per-t row bit masks
    __shared__ float4             LUT[512];           // conv1 per 9-bit pat
    __shared__ float              S2[4 * E1A];        // channel spike counts

    const int tid  = threadIdx.x;
    const int lane = tid & 31;
    const int wrp  = tid >> 5;
    const int tx0  = blockIdx.x * TILE;
    const int ty0  = blockIdx.y * TILE;
    const int b    = blockIdx.z;
    const int ob   = (b * HH + ty0) * WW + tx0;   // output tile base

    // ---- 3x3 neighbor-tile flag check (covers the 36x36 halo) ----------
    if (tid < 32) {
        unsigned fl = 0u;
        if (tid < 9) {
            int ty = (int)blockIdx.y + tid / 3 - 1;
            int tx = (int)blockIdx.x + tid % 3 - 1;
            if ((unsigned)ty < 8u && (unsigned)tx < 8u)
                fl = g_any[(b * 8 + ty) * 8 + tx];
        }
        fl = __reduce_or_sync(0xffffffffu, fl);
        if (tid == 0) FLAG = fl;
    }
    __syncthreads();

    if (FLAG == 0u) {
        // No layer-1 spikes in this tile's halo at any t => c1 == 0 always
        // => v2 decays from 0 => no layer-2 spikes => out == 0 exactly.
        if (tid < 256) {
            int r = tid >> 3;
            int c = (tid & 7) * 4;
            *(float4*)(out + ob + r * WW + c) = make_float4(0.f, 0.f, 0.f, 0.f);
        }
        return;
    }

    // =================== spiking path (general inputs) ==================
    // load 36x36 spike words (halo-2, zero outside image)
    unsigned myor = 0u;
#pragma unroll
    for (int i = 0; i < NS2; ++i) {
        int idx = tid + i * NTH;
        unsigned short w = 0;
        if (idx < E2A) {
            int r = idx / E2W;
            int c = idx - r * E2W;
            int gy = ty0 + r - 2;
            int gx = tx0 + c - 2;
            if (((unsigned)gy < HH) && ((unsigned)gx < WW))
                w = g_spk[(b * HH + gy) * WW + gx];
            SW[idx] = w;
        }
        myor |= w;
    }
    unsigned wor = __reduce_or_sync(0xffffffffu, myor);
    if (lane == 0) WANY[wrp] = wor;

    // build conv1 LUT: bit (ky*3+kx) set => s1==1 at that tap
    {
        float w1r[36];
#pragma unroll
        for (int i = 0; i < 36; ++i) w1r[i] = __ldg(w1 + i);
        for (int p = tid; p < 512; p += NTH) {
            float a0 = 0.f, a1 = 0.f, a2 = 0.f, a3 = 0.f;
#pragma unroll
            for (int tap = 0; tap < 9; ++tap) {
                if (p & (1 << tap)) {
                    a0 += w1r[tap];
                    a1 += w1r[9  + tap];
                    a2 += w1r[18 + tap];
                    a3 += w1r[27 + tap];
                }
            }
            LUT[p] = make_float4(a0, a1, a2, a3);
        }
    }
    __syncthreads();
    unsigned f2 = (lane < NWARPS) ? WANY[lane] : 0u;
    const unsigned tany = __reduce_or_sync(0xffffffffu, f2);

    // repack: ROWS[t][r] = 36-bit spike row mask for timestep t
    for (int task = tid; task < T_STEPS * E2W; task += NTH) {
        int t = task / E2W;
        int r = task - t * E2W;
        if ((tany >> t) & 1u) {
            unsigned long long m = 0ull;
            const unsigned short* sr = SW + r * E2W;
#pragma unroll 4
            for (int c = 0; c < E2W; ++c)
                m |= (unsigned long long)((sr[c] >> t) & 1u) << c;
            ROWS[t][r] = m;
        }
    }
    __syncthreads();   // LUT + ROWS ready

    // this thread owns a 2x2 block of E1 pixels
    const bool active = (tid < NBLK);
    const int  br = tid / 17;
    const int  bc = tid - br * 17;
    const int  R  = 2 * br;              // E1 row of top-left pixel
    const int  C  = 2 * bc;              // E1 col of top-left pixel (<=32)

    float    v2[4][4];
    unsigned ssum[4];
#pragma unroll
    for (int p = 0; p < 4; ++p) {
        ssum[p] = 0u;
#pragma unroll
        for (int ch = 0; ch < 4; ++ch) v2[p][ch] = 0.0f;
    }

    // temporal loop: ROWS read-only => NO barriers inside
#pragma unroll 1
    for (int t = 0; t < T_STEPS; ++t) {
        if ((tany >> t) & 1u) {
            if (active) {
                const uint2* R32 = (const uint2*)ROWS[t];
                uint2 r0 = R32[R];
                uint2 r1 = R32[R + 1];
                uint2 r2 = R32[R + 2];
                uint2 r3 = R32[R + 3];
                unsigned u0 = __funnelshift_rc(r0.x, r0.y, C) & 15u;
                unsigned u1 = __funnelshift_rc(r1.x, r1.y, C) & 15u;
                unsigned u2 = __funnelshift_rc(r2.x, r2.y, C) & 15u;
                unsigned u3 = __funnelshift_rc(r3.x, r3.y, C) & 15u;

                unsigned pat[4];
                pat[0] = (u0 & 7u) | ((u1 & 7u) << 3) | ((u2 & 7u) << 6);
                pat[1] = ((u0 >> 1) & 7u) | (((u1 >> 1) & 7u) << 3) | (((u2 >> 1) & 7u) << 6);
                pat[2] = (u1 & 7u) | ((u2 & 7u) << 3) | ((u3 & 7u) << 6);
                pat[3] = ((u1 >> 1) & 7u) | (((u2 >> 1) & 7u) << 3) | (((u3 >> 1) & 7u) << 6);

#pragma unroll
                for (int p = 0; p < 4; ++p) {
                    float4 cc = LUT[pat[p]];
                    unsigned add = 0u;
                    float v;
                    v = fmaf(cc.x - v2[p][0], 0.5f, v2[p][0]);
                    if (v >= 1.0f) { add += 1u;       v = 0.0f; }
                    v2[p][0] = v;
                    v = fmaf(cc.y - v2[p][1], 0.5f, v2[p][1]);
                    if (v >= 1.0f) { add += 1u << 8;  v = 0.0f; }
                    v2[p][1] = v;
                    v = fmaf(cc.z - v2[p][2], 0.5f, v2[p][2]);
                    if (v >= 1.0f) { add += 1u << 16; v = 0.0f; }
                    v2[p][2] = v;
                    v = fmaf(cc.w - v2[p][3], 0.5f, v2[p][3]);
                    if (v >= 1.0f) { add += 1u << 24; v = 0.0f; }
                    v2[p][3] = v;
                    ssum[p] += add;
                }
            }
        } else {
            // empty step: c1 == 0 => v2' = v2/2; invariant v2 < 1 gives
            // v2/2 < V_TH: no spike possible, ssum unchanged.
#pragma unroll
            for (int p = 0; p < 4; ++p) {
#pragma unroll
                for (int ch = 0; ch < 4; ++ch) v2[p][ch] *= 0.5f;
            }
        }
    }
    __syncthreads();

    // unpack spike counts into S2 planes (0 for out-of-image px)
    if (active) {
#pragma unroll
        for (int dr = 0; dr < 2; ++dr) {
#pragma unroll
            for (int dc = 0; dc < 2; ++dc) {
                int r = R + dr, c = C + dc;
                int gy = ty0 + r - 1;
                int gx = tx0 + c - 1;
                bool ok = ((unsigned)gy < HH) && ((unsigned)gx < WW);
                unsigned pk = ok ? ssum[dr * 2 + dc] : 0u;
                int idx = r * E1W + c;
                S2[idx]           = (float)( pk         & 255u);
                S2[E1A     + idx] = (float)((pk >> 8 )  & 255u);
                S2[2 * E1A + idx] = (float)((pk >> 16)  & 255u);
                S2[3 * E1A + idx] = (float)((pk >> 24)  & 255u);
            }
        }
    }
    __syncthreads();

    // conv2 (3x3, 4->1ch) ONCE on summed spikes; divide by T
    // mean_t conv(s2_t, w2) = conv(sum_t s2_t, w2) / T   (linearity)
    float w2r[36];
#pragma unroll
    for (int i = 0; i < 36; ++i) w2r[i] = __ldg(w2 + i);

    const float invT = 1.0f / (float)T_STEPS;
#pragma unroll
    for (int i = 0; i < 4; ++i) {
        int idx = tid + i * NTH;
        if (idx < TILE * TILE) {
            int r = idx >> 5;
            int c = idx & 31;
            int base = r * E1W + c;
            float acc = 0.0f;
#pragma unroll
            for (int ch = 0; ch < 4; ++ch) {
#pragma unroll
                for (int ky = 0; ky < 3; ++ky) {
#pragma unroll
                    for (int kx = 0; kx < 3; ++kx) {
                        acc = fmaf(S2[ch * E1A + base + ky * E1W + kx],
                                   w2r[ch * 9 + ky * 3 + kx], acc);
                    }
                }
            }
            out[ob + r * WW + c] = acc * invT;
        }
    }
}

extern "C" void kernel_launch(void* const* d_in, const int* in_sizes, int n_in,
                              void* d_out, int out_size)
{
    const float* x  = (const float*)d_in[0];
    const float* w1 = (const float*)d_in[1];
    const float* w2 = (const float*)d_in[2];
    float* out = (float*)d_out;

    zero_flags_kernel<<<NTILES / 256, 256>>>();
    lif1_kernel<<<NPIX / (K1TH * 4), K1TH>>>(x);

    dim3 grid(WW / TILE, HH / TILE, BATCH);   // (8, 8, 32)
    lif2_kernel<<<grid, NTH>>>(w1, w2, out);
}

// round 15
// speedup vs baseline: 1.0693x; 1.0693x over previous
#include <cuda_runtime.h>

#define T_STEPS 16
#define BATCH   32
#define HH      256
#define WW      256
#define NPIX    (BATCH*HH*WW)       // 2,097,152 pixels
#define TILE    32
#define E2W     36                  // tile + 2*2 halo (layer-1 spike extent)
#define E1W     34                  // tile + 2*1 halo (layer-2 extent)
#define E2A     (E2W*E2W)           // 1296
#define E1A     (E1W*E1W)           // 1156
#define NTH     320                 // K2: 10 warps
#define NWARPS  (NTH/32)
#define NS2     5                   // ceil(1296/320)
#define NBLK    289                 // 17x17 2x2-pixel blocks covering E1
#define K1TH    256                 // K1 threads per block
#define NROWG   (NPIX/128)          // 16384 row-group flag slots

// 4 MB spike scratch: bit t of g_spk[p] = layer-1 spike at pixel p, time t
__device__ unsigned short g_spk[NPIX];
// per-(row,128px-group) any-spike flags; OVERWRITTEN (not accumulated) by
// every K1 run => replay-safe with no zeroing kernel.
__device__ unsigned g_rowany[NROWG];

// ========================= K1: pointwise LIF-1 ==========================
// 4 pixels per thread via float4: 16 LDG.128 (MLP=16), recurrence in regs,
// one 8-byte packed spike store. Each warp covers 128 consecutive pixels of
// one row and unconditionally writes its any-spike flag slot.
__global__ void __launch_bounds__(K1TH) lif1_kernel(const float* __restrict__ x)
{
    const int tid = threadIdx.x;
    const int gt  = blockIdx.x * K1TH + tid;
    const int p4  = gt * 4;

    float4 xv[T_STEPS];
#pragma unroll
    for (int t = 0; t < T_STEPS; ++t)
        xv[t] = __ldg((const float4*)(x + (size_t)t * NPIX + p4));

    float v0 = 0.f, v1 = 0.f, v2 = 0.f, v3 = 0.f;
    unsigned b0 = 0u, b1 = 0u, b2 = 0u, b3 = 0u;
#pragma unroll
    for (int t = 0; t < T_STEPS; ++t) {
        // v = v + (x-v)/2 : single-rounded, bit-identical to reference
        v0 = fmaf(xv[t].x - v0, 0.5f, v0);
        if (v0 >= 1.0f) { b0 |= 1u << t; v0 = 0.0f; }
        v1 = fmaf(xv[t].y - v1, 0.5f, v1);
        if (v1 >= 1.0f) { b1 |= 1u << t; v1 = 0.0f; }
        v2 = fmaf(xv[t].z - v2, 0.5f, v2);
        if (v2 >= 1.0f) { b2 |= 1u << t; v2 = 0.0f; }
        v3 = fmaf(xv[t].w - v3, 0.5f, v3);
        if (v3 >= 1.0f) { b3 |= 1u << t; v3 = 0.0f; }
    }

    uint2 pk;
    pk.x = b0 | (b1 << 16);
    pk.y = b2 | (b3 << 16);
    *(uint2*)(g_spk + p4) = pk;       // 8B aligned (p4 % 4 == 0)

    // warp = 32 threads * 4 px = 128 consecutive px of one row
    unsigned m = __reduce_or_sync(0xffffffffu, b0 | b1 | b2 | b3);
    if ((tid & 31) == 0)
        g_rowany[gt >> 5] = m;        // overwrite: 0 or nonzero, every run
}

// ==================== K2: bit-domain LIF-2 + convs ======================
__global__ void __launch_bounds__(NTH, 3) lif2_kernel(
    const float* __restrict__ w1,
    const float* __restrict__ w2,
    float* __restrict__ out)
{
    __shared__ unsigned short     SW[E2A];            // spike words (16 t)
    __shared__ unsigned           WANY[NWARPS];
    __shared__ unsigned           FLAGW[3];
    __shared__ unsigned long long ROWS[T_STEPS][E2W]; // per-t row bit masks
    __shared__ float4             LUT[512];           // conv1 per 9-bit pat
    __shared__ float              S2[4 * E1A];        // channel spike counts

    const int tid  = threadIdx.x;
    const int lane = tid & 31;
    const int wrp  = tid >> 5;
    const int tx0  = blockIdx.x * TILE;
    const int ty0  = blockIdx.y * TILE;
    const int b    = blockIdx.z;
    const int ob   = (b * HH + ty0) * WW + tx0;   // output tile base

    // ---- halo flag check: rows [ty0-2, ty0+33] x groups of 128 px ------
    // group range covering x in [tx0-2, tx0+33]
    const int g0 = (tx0 >= 2 ? tx0 - 2 : 0) >> 7;
    const int g1 = ((tx0 + 33 <= 255) ? tx0 + 33 : 255) >> 7;
    const int ng = g1 - g0 + 1;                    // 1 or 2
    if (wrp < 3) {                                 // 96 threads cover <=72
        unsigned fl = 0u;
        int idx = tid;                             // 0..95
        if (idx < 36 * ng) {
            int ry = ty0 - 2 + idx / ng;
            int g  = g0 + idx % ng;
            if ((unsigned)ry < (unsigned)HH)
                fl = g_rowany[(b * HH + ry) * 2 + g];
        }
        fl = __reduce_or_sync(0xffffffffu, fl);
        if (lane == 0) FLAGW[wrp] = fl;
    }
    __syncthreads();
    const unsigned FLAG = FLAGW[0] | FLAGW[1] | FLAGW[2];

    if (FLAG == 0u) {
        // No layer-1 spikes in this tile's halo at any t => c1 == 0 always
        // => v2 decays from 0 => no layer-2 spikes => out == 0 exactly.
        if (tid < 256) {
            int r = tid >> 3;
            int c = (tid & 7) * 4;
            *(float4*)(out + ob + r * WW + c) = make_float4(0.f, 0.f, 0.f, 0.f);
        }
        return;
    }

    // =================== spiking path (general inputs) ==================
    // load 36x36 spike words (halo-2, zero outside image)
    unsigned myor = 0u;
#pragma unroll
    for (int i = 0; i < NS2; ++i) {
        int idx = tid + i * NTH;
        unsigned short w = 0;
        if (idx < E2A) {
            int r = idx / E2W;
            int c = idx - r * E2W;
            int gy = ty0 + r - 2;
            int gx = tx0 + c - 2;
            if (((unsigned)gy < HH) && ((unsigned)gx < WW))
                w = g_spk[(b * HH + gy) * WW + gx];
            SW[idx] = w;
        }
        myor |= w;
    }
    unsigned wor = __reduce_or_sync(0xffffffffu, myor);
    if (lane == 0) WANY[wrp] = wor;

    // build conv1 LUT: bit (ky*3+kx) set => s1==1 at that tap
    {
        float w1r[36];
#pragma unroll
        for (int i = 0; i < 36; ++i) w1r[i] = __ldg(w1 + i);
        for (int p = tid; p < 512; p += NTH) {
            float a0 = 0.f, a1 = 0.f, a2 = 0.f, a3 = 0.f;
#pragma unroll
            for (int tap = 0; tap < 9; ++tap) {
                if (p & (1 << tap)) {
                    a0 += w1r[tap];
                    a1 += w1r[9  + tap];
                    a2 += w1r[18 + tap];
                    a3 += w1r[27 + tap];
                }
            }
            LUT[p] = make_float4(a0, a1, a2, a3);
        }
    }
    __syncthreads();
    unsigned f2 = (lane < NWARPS) ? WANY[lane] : 0u;
    const unsigned tany = __reduce_or_sync(0xffffffffu, f2);

    // repack: ROWS[t][r] = 36-bit spike row mask for timestep t
    for (int task = tid; task < T_STEPS * E2W; task += NTH) {
        int t = task / E2W;
        int r = task - t * E2W;
        if ((tany >> t) & 1u) {
            unsigned long long m = 0ull;
            const unsigned short* sr = SW + r * E2W;
#pragma unroll 4
            for (int c = 0; c < E2W; ++c)
                m |= (unsigned long long)((sr[c] >> t) & 1u) << c;
            ROWS[t][r] = m;
        }
    }
    __syncthreads();   // LUT + ROWS ready

    // this thread owns a 2x2 block of E1 pixels
    const bool active = (tid < NBLK);
    const int  br = tid / 17;
    const int  bc = tid - br * 17;
    const int  R  = 2 * br;              // E1 row of top-left pixel
    const int  C  = 2 * bc;              // E1 col of top-left pixel (<=32)

    float    v2[4][4];
    unsigned ssum[4];
#pragma unroll
    for (int p = 0; p < 4; ++p) {
        ssum[p] = 0u;
#pragma unroll
        for (int ch = 0; ch < 4; ++ch) v2[p][ch] = 0.0f;
    }

    // temporal loop: ROWS read-only => NO barriers inside
#pragma unroll 1
    for (int t = 0; t < T_STEPS; ++t) {
        if ((tany >> t) & 1u) {
            if (active) {
                const uint2* R32 = (const uint2*)ROWS[t];
                uint2 r0 = R32[R];
                uint2 r1 = R32[R + 1];
                uint2 r2 = R32[R + 2];
                uint2 r3 = R32[R + 3];
                unsigned u0 = __funnelshift_rc(r0.x, r0.y, C) & 15u;
                unsigned u1 = __funnelshift_rc(r1.x, r1.y, C) & 15u;
                unsigned u2 = __funnelshift_rc(r2.x, r2.y, C) & 15u;
                unsigned u3 = __funnelshift_rc(r3.x, r3.y, C) & 15u;

                unsigned pat[4];
                pat[0] = (u0 & 7u) | ((u1 & 7u) << 3) | ((u2 & 7u) << 6);
                pat[1] = ((u0 >> 1) & 7u) | (((u1 >> 1) & 7u) << 3) | (((u2 >> 1) & 7u) << 6);
                pat[2] = (u1 & 7u) | ((u2 & 7u) << 3) | ((u3 & 7u) << 6);
                pat[3] = ((u1 >> 1) & 7u) | (((u2 >> 1) & 7u) << 3) | (((u3 >> 1) & 7u) << 6);

#pragma unroll
                for (int p = 0; p < 4; ++p) {
                    float4 cc = LUT[pat[p]];
                    unsigned add = 0u;
                    float v;
                    v = fmaf(cc.x - v2[p][0], 0.5f, v2[p][0]);
                    if (v >= 1.0f) { add += 1u;       v = 0.0f; }
                    v2[p][0] = v;
                    v = fmaf(cc.y - v2[p][1], 0.5f, v2[p][1]);
                    if (v >= 1.0f) { add += 1u << 8;  v = 0.0f; }
                    v2[p][1] = v;
                    v = fmaf(cc.z - v2[p][2], 0.5f, v2[p][2]);
                    if (v >= 1.0f) { add += 1u << 16; v = 0.0f; }
                    v2[p][2] = v;
                    v = fmaf(cc.w - v2[p][3], 0.5f, v2[p][3]);
                    if (v >= 1.0f) { add += 1u << 24; v = 0.0f; }
                    v2[p][3] = v;
                    ssum[p] += add;
                }
            }
        } else {
            // empty step: c1 == 0 => v2' = v2/2; invariant v2 < 1 gives
            // v2/2 < V_TH: no spike possible, ssum unchanged.
#pragma unroll
            for (int p = 0; p < 4; ++p) {
#pragma unroll
                for (int ch = 0; ch < 4; ++ch) v2[p][ch] *= 0.5f;
            }
        }
    }
    __syncthreads();

    // unpack spike counts into S2 planes (0 for out-of-image px)
    if (active) {
#pragma unroll
        for (int dr = 0; dr < 2; ++dr) {
#pragma unroll
            for (int dc = 0; dc < 2; ++dc) {
                int r = R + dr, c = C + dc;
                int gy = ty0 + r - 1;
                int gx = tx0 + c - 1;
                bool ok = ((unsigned)gy < HH) && ((unsigned)gx < WW);
                unsigned pk = ok ? ssum[dr * 2 + dc] : 0u;
                int idx = r * E1W + c;
                S2[idx]           = (float)( pk         & 255u);
                S2[E1A     + idx] = (float)((pk >> 8 )  & 255u);
                S2[2 * E1A + idx] = (float)((pk >> 16)  & 255u);
                S2[3 * E1A + idx] = (float)((pk >> 24)  & 255u);
            }
        }
    }
    __syncthreads();

    // conv2 (3x3, 4->1ch) ONCE on summed spikes; divide by T
    // mean_t conv(s2_t, w2) = conv(sum_t s2_t, w2) / T   (linearity)
    float w2r[36];
#pragma unroll
    for (int i = 0; i < 36; ++i) w2r[i] = __ldg(w2 + i);

    const float invT = 1.0f / (float)T_STEPS;
#pragma unroll
    for (int i = 0; i < 4; ++i) {
        int idx = tid + i * NTH;
        if (idx < TILE * TILE) {
            int r = idx >> 5;
            int c = idx & 31;
            int base = r * E1W + c;
            float acc = 0.0f;
#pragma unroll
            for (int ch = 0; ch < 4; ++ch) {
#pragma unroll
                for (int ky = 0; ky < 3; ++ky) {
#pragma unroll
                    for (int kx = 0; kx < 3; ++kx) {
                        acc = fmaf(S2[ch * E1A + base + ky * E1W + kx],
                                   w2r[ch * 9 + ky * 3 + kx], acc);
                    }
                }
            }
            out[ob + r * WW + c] = acc * invT;
        }
    }
}

extern "C" void kernel_launch(void* const* d_in, const int* in_sizes, int n_in,
                              void* d_out, int out_size)
{
    const float* x  = (const float*)d_in[0];
    const float* w1 = (const float*)d_in[1];
    const float* w2 = (const float*)d_in[2];
    float* out = (float*)d_out;

    lif1_kernel<<<NPIX / (K1TH * 4), K1TH>>>(x);

    dim3 grid(WW / TILE, HH / TILE, BATCH);   // (8, 8, 32)
    lif2_kernel<<<grid, NTH>>>(w1, w2, out);
}